// round 4
// baseline (speedup 1.0000x reference)
#include <cuda_runtime.h>
#include <math.h>

#define NROW 8192
#define ALPHA 0.2f

// packed fp32x2 FMA (Blackwell): d = a*b + d, lanewise on 2 packed floats
#define FMA_F32X2(d, a, b) \
  asm("fma.rn.f32x2 %0, %1, %2, %0;" : "+l"(d) : "l"(a), "l"(b))
#define UNPACK_F32X2(lo, hi, v) \
  asm("mov.b64 {%0, %1}, %2;" : "=f"(lo), "=f"(hi) : "l"(v))

// ---- scratch (static device globals; no allocation) ----
__device__ __align__(16) float g_h1[NROW * 256];   // layer1 linear out
__device__ __align__(16) float g_x2[NROW * 256];   // elu(elu(attn1 @ h1))
__device__ __align__(16) float g_h2[NROW * 64];    // layer2 linear out
__device__ float g_hl[NROW];
__device__ float g_hr[NROW];

__device__ __forceinline__ float elu1(float z) { return z > 0.f ? z : expm1f(z); }

// ============================================================================
// C[M,Fd] = A[M,K] @ W[Fd,K]^T + b      (64x64 tile, 4x4 per thread)
// ============================================================================
__global__ void __launch_bounds__(256) gemm_bias_k(
    const float* __restrict__ A, const float* __restrict__ W,
    const float* __restrict__ b, float* __restrict__ C, int K, int Fd) {
  __shared__ float As[64][17];
  __shared__ float Ws[64][17];
  int tid = threadIdx.x;
  int tx = tid & 15, ty = tid >> 4;
  int mbase = blockIdx.y * 64, fbase = blockIdx.x * 64;
  float acc[4][4] = {};
  for (int k0 = 0; k0 < K; k0 += 16) {
#pragma unroll
    for (int idx = tid; idx < 1024; idx += 256) {
      int r = idx >> 4, k = idx & 15;
      As[r][k] = A[(size_t)(mbase + r) * K + k0 + k];
      Ws[r][k] = W[(size_t)(fbase + r) * K + k0 + k];
    }
    __syncthreads();
#pragma unroll
    for (int k = 0; k < 16; k++) {
      float a[4], w[4];
#pragma unroll
      for (int r = 0; r < 4; r++) a[r] = As[ty * 4 + r][k];
#pragma unroll
      for (int c = 0; c < 4; c++) w[c] = Ws[tx * 4 + c][k];
#pragma unroll
      for (int r = 0; r < 4; r++)
#pragma unroll
        for (int c = 0; c < 4; c++) acc[r][c] += a[r] * w[c];
    }
    __syncthreads();
  }
#pragma unroll
  for (int r = 0; r < 4; r++) {
    int row = mbase + ty * 4 + r;
#pragma unroll
    for (int c = 0; c < 4; c++) {
      int col = fbase + tx * 4 + c;
      C[(size_t)row * Fd + col] = acc[r][c] + b[col];
    }
  }
}

// ============================================================================
// hl[i] = dot(h[i,:], a[0:F]);  hr[i] = dot(h[i,:], a[F:2F])
// ============================================================================
__global__ void __launch_bounds__(256) attn_vec_k(
    const float* __restrict__ h, const float* __restrict__ a, int Fd,
    float* __restrict__ hl, float* __restrict__ hr) {
  int i = blockIdx.x, t = threadIdx.x;
  float pl = 0.f, pr = 0.f;
  if (t < Fd) {
    float x = h[(size_t)i * Fd + t];
    pl = x * a[t];
    pr = x * a[Fd + t];
  }
  __shared__ float sl[256], sr[256];
  sl[t] = pl; sr[t] = pr;
  __syncthreads();
  for (int s = 128; s > 0; s >>= 1) {
    if (t < s) { sl[t] += sl[t + s]; sr[t] += sr[t + s]; }
    __syncthreads();
  }
  if (t == 0) { hl[i] = sl[0]; hr[i] = sr[0]; }
}

// ============================================================================
// Fused attention: out[MT rows, F] = softmax(mask(leaky(score))) @ h + epilogue
// Unnormalized weights w = adj ? exp(leaky(hl_i+hr_j+ab)) : 0 (scores are O(1),
// no overflow; exp(NEG) underflows to 0 exactly, matching the reference).
// Row-sum s accumulated in the w-phase; normalization applied in the epilogue.
// Packed f32x2 FFMA2 inner loop; ws duplicated (w,w) so weights arrive packed.
// EPI==1: elu(elu(.)) -> x2     EPI==2: elu(.) then per-row log_softmax -> out
// ============================================================================
template <int F, int MT, int EPI>
__global__ void __launch_bounds__(256, 3) attn_gemm_k(
    const int* __restrict__ adj, const float* __restrict__ h,
    const float* __restrict__ hl, const float* __restrict__ hr,
    const float* __restrict__ ab, float* __restrict__ out) {
  constexpr int KC = 16;
  constexpr int CG = F / 4;              // float4 column groups
  constexpr int IG = 256 / CG;           // i-groups
  constexpr int IPT = MT / IG;           // rows per thread (even)
  constexpr int HPT = (KC * F / 4) / 256;  // float4 per thread for h chunk
  __shared__ __align__(16) float hs[KC][F];
  __shared__ __align__(16) float2 ws2[KC][MT + 2];  // (w,w) dup; stride %16==0
  __shared__ float ssum[MT];

  int tid = threadIdx.x;
  int ibase = blockIdx.x * MT;
  int cg = tid % CG, ig = tid / CG;
  int iw = tid >> 2;                     // w-phase row (KC/4 = 4 thr/row)
  int jw = (tid & 3) * 4;                // k offset within chunk
  bool wact = iw < MT;

  float hli = 0.f;
  if (wact) hli = hl[ibase + iw] + ab[0];
  float s_part = 0.f;

  const float4* h4 = (const float4*)h;
  unsigned long long acc2[IPT][2] = {};  // packed (f32,f32) accumulators

  for (int k0 = 0; k0 < NROW; k0 += KC) {
    // global prefetch into registers BEFORE the barrier: overlaps the
    // previous chunk's FMA phase with L2/DRAM latency.
    float4 hreg[HPT];
#pragma unroll
    for (int t = 0; t < HPT; t++) {
      int idx = tid + t * 256;
      hreg[t] = h4[(size_t)(k0 + idx / (F / 4)) * (F / 4) + idx % (F / 4)];
    }
    int4 av;
    float4 hrv;
    if (wact) {
      av = *(const int4*)(adj + (size_t)(ibase + iw) * NROW + k0 + jw);
      hrv = *(const float4*)(hr + k0 + jw);
    }

    __syncthreads();  // previous chunk's FMA done; smem free
#pragma unroll
    for (int t = 0; t < HPT; t++) {
      int idx = tid + t * 256;
      ((float4*)&hs[idx / (F / 4)][0])[idx % (F / 4)] = hreg[t];
    }
    if (wact) {
      float e, w;
      e = hli + hrv.x; e = e > 0.f ? e : ALPHA * e;
      w = av.x ? __expf(e) : 0.f; ws2[jw + 0][iw] = make_float2(w, w); s_part += w;
      e = hli + hrv.y; e = e > 0.f ? e : ALPHA * e;
      w = av.y ? __expf(e) : 0.f; ws2[jw + 1][iw] = make_float2(w, w); s_part += w;
      e = hli + hrv.z; e = e > 0.f ? e : ALPHA * e;
      w = av.z ? __expf(e) : 0.f; ws2[jw + 2][iw] = make_float2(w, w); s_part += w;
      e = hli + hrv.w; e = e > 0.f ? e : ALPHA * e;
      w = av.w ? __expf(e) : 0.f; ws2[jw + 3][iw] = make_float2(w, w); s_part += w;
    }
    __syncthreads();

#pragma unroll
    for (int k = 0; k < KC; k++) {
      // one LDS.128: 4 h-columns as 2 packed f32x2
      ulonglong2 hp = ((const ulonglong2*)&hs[k][0])[cg];
#pragma unroll
      for (int r2 = 0; r2 < IPT / 2; r2++) {
        // one LDS.128 broadcast: duplicated weights for 2 adjacent rows
        ulonglong2 wp = ((const ulonglong2*)&ws2[k][0])[ig * (IPT / 2) + r2];
        FMA_F32X2(acc2[2 * r2 + 0][0], wp.x, hp.x);
        FMA_F32X2(acc2[2 * r2 + 0][1], wp.x, hp.y);
        FMA_F32X2(acc2[2 * r2 + 1][0], wp.y, hp.x);
        FMA_F32X2(acc2[2 * r2 + 1][1], wp.y, hp.y);
      }
    }
  }

  // reduce row-sums across the 4 w-phase lanes of each row (contiguous lanes)
  s_part += __shfl_xor_sync(0xFFFFFFFFu, s_part, 1);
  s_part += __shfl_xor_sync(0xFFFFFFFFu, s_part, 2);
  if (wact && (tid & 3) == 0) ssum[iw] = s_part;
  __syncthreads();

#pragma unroll
  for (int r = 0; r < IPT; r++) {
    int lrow = ig * IPT + r;
    float si = 1.f / ssum[lrow];
    float z[4];
    UNPACK_F32X2(z[0], z[1], acc2[r][0]);
    UNPACK_F32X2(z[2], z[3], acc2[r][1]);
#pragma unroll
    for (int q = 0; q < 4; q++) z[q] = elu1(z[q] * si);

    float* op = out + (size_t)(ibase + lrow) * F + cg * 4;
    if (EPI == 1) {
#pragma unroll
      for (int q = 0; q < 4; q++) op[q] = elu1(z[q]);
    } else {
      // fused per-row log_softmax: the CG=16 threads owning this row are a
      // contiguous, aligned 16-lane shuffle group.
      float m = fmaxf(fmaxf(z[0], z[1]), fmaxf(z[2], z[3]));
#pragma unroll
      for (int d = CG / 2; d >= 1; d >>= 1)
        m = fmaxf(m, __shfl_xor_sync(0xFFFFFFFFu, m, d));
      float s = __expf(z[0] - m) + __expf(z[1] - m) +
                __expf(z[2] - m) + __expf(z[3] - m);
#pragma unroll
      for (int d = CG / 2; d >= 1; d >>= 1)
        s += __shfl_xor_sync(0xFFFFFFFFu, s, d);
      float l = m + logf(s);
#pragma unroll
      for (int q = 0; q < 4; q++) op[q] = z[q] - l;
    }
  }
}

// ============================================================================
extern "C" void kernel_launch(void* const* d_in, const int* in_sizes, int n_in,
                              void* d_out, int out_size) {
  const float* x   = (const float*)d_in[0];
  const int*   adj = (const int*)d_in[1];
  const float* W1  = (const float*)d_in[2];
  const float* b1  = (const float*)d_in[3];
  const float* a1  = (const float*)d_in[4];
  const float* ab1 = (const float*)d_in[5];
  const float* W2  = (const float*)d_in[6];
  const float* b2  = (const float*)d_in[7];
  const float* a2  = (const float*)d_in[8];
  const float* ab2 = (const float*)d_in[9];
  float* out = (float*)d_out;

  float *h1, *x2, *h2, *hl, *hr;
  cudaGetSymbolAddress((void**)&h1, g_h1);
  cudaGetSymbolAddress((void**)&x2, g_x2);
  cudaGetSymbolAddress((void**)&h2, g_h2);
  cudaGetSymbolAddress((void**)&hl, g_hl);
  cudaGetSymbolAddress((void**)&hr, g_hr);

  // ---- layer 1 ----
  gemm_bias_k<<<dim3(256 / 64, NROW / 64), 256>>>(x, W1, b1, h1, 512, 256);
  attn_vec_k<<<NROW, 256>>>(h1, a1, 256, hl, hr);
  attn_gemm_k<256, 32, 1><<<NROW / 32, 256>>>(adj, h1, hl, hr, ab1, x2);

  // ---- layer 2 (log_softmax fused into the attention epilogue) ----
  gemm_bias_k<<<dim3(64 / 64, NROW / 64), 256>>>(x2, W2, b2, h2, 256, 64);
  attn_vec_k<<<NROW, 256>>>(h2, a2, 64, hl, hr);
  attn_gemm_k<64, 64, 2><<<NROW / 64, 256>>>(adj, h2, hl, hr, ab2, out);
}